// round 6
// baseline (speedup 1.0000x reference)
#include <cuda_runtime.h>
#include <cuda_bf16.h>
#include <math.h>
#include <stdint.h>

#define BATCH 8192
#define D1    129
#define KDIM  128
#define TM    128
#define TN    128

#define TC_F    1.00000095367431640625f   // fp32(1 + 1e-6)
#define PEXP    (-14.285714285714285714f) // -1/0.07
#define TCUT    1.4f                      // skip threshold: e(1.4)=4.2e-6
#define E_CLAMP 0.98046380f               // exp(-acosh(1+2^-20)/0.07), exact

// smem: A/B tiles with rows padded to 272B (17 x 16B groups -> conflict-free ldmatrix)
#define LDT_B   272u
#define SM_A    0u
#define SM_B    34816u
#define SM_A0   69632u
#define SM_B0   70144u
#define SMEM_BYTES 70656

// ---- device scratch (allocation-free) ----
__device__ __align__(256) __nv_bfloat16 g_A[BATCH * KDIM];
__device__ __align__(256) __nv_bfloat16 g_B[BATCH * KDIM];
__device__ float g_a0[BATCH], g_b0[BATCH];
__device__ float g_rowsum[BATCH], g_colsum[BATCH];
__device__ float g_loss;
__device__ unsigned g_ticket;

__device__ __forceinline__ uint32_t smem_u32(const void* p) {
    uint32_t a;
    asm("{ .reg .u64 t; cvta.to.shared.u64 t, %1; cvt.u32.u64 %0, t; }" : "=r"(a) : "l"(p));
    return a;
}
__device__ __forceinline__ float f_sqrt(float x) { float r; asm("sqrt.approx.f32 %0, %1;" : "=f"(r) : "f"(x)); return r; }
__device__ __forceinline__ float f_lg2(float x)  { float r; asm("lg2.approx.f32 %0, %1;"  : "=f"(r) : "f"(x)); return r; }
__device__ __forceinline__ float f_ex2(float x)  { float r; asm("ex2.approx.f32 %0, %1;"  : "=f"(r) : "f"(x)); return r; }

__device__ __forceinline__ void ldsm_x4(uint32_t& r0, uint32_t& r1, uint32_t& r2, uint32_t& r3, uint32_t addr) {
    asm volatile("ldmatrix.sync.aligned.m8n8.x4.shared.b16 {%0,%1,%2,%3}, [%4];"
                 : "=r"(r0), "=r"(r1), "=r"(r2), "=r"(r3) : "r"(addr));
}
__device__ __forceinline__ void mma16816(float* c, const uint32_t* a, const uint32_t* b) {
    asm volatile("mma.sync.aligned.m16n8k16.row.col.f32.bf16.bf16.f32 "
                 "{%0,%1,%2,%3}, {%4,%5,%6,%7}, {%8,%9}, {%0,%1,%2,%3};"
                 : "+f"(c[0]), "+f"(c[1]), "+f"(c[2]), "+f"(c[3])
                 : "r"(a[0]), "r"(a[1]), "r"(a[2]), "r"(a[3]), "r"(b[0]), "r"(b[1]));
}

// ---- prep: bf16 operands (k=1..128), k=0 coords, zero accumulators ----
__global__ void prep_kernel(const float* __restrict__ z1, const float* __restrict__ z2) {
    int idx = blockIdx.x * 256 + threadIdx.x;
    if (idx < BATCH * KDIM) {
        int i = idx >> 7, kk = idx & 127;
        g_A[idx] = __float2bfloat16(z1[(size_t)i * D1 + 1 + kk]);
        g_B[idx] = __float2bfloat16(z2[(size_t)i * D1 + 1 + kk]);
    }
    if (idx < BATCH) {
        g_a0[idx] = z1[(size_t)idx * D1];
        g_b0[idx] = z2[(size_t)idx * D1];
        g_rowsum[idx] = 0.f;
        g_colsum[idx] = 0.f;
    }
    if (idx == 0) { g_loss = 0.f; g_ticket = 0u; }
}

// ---- fused HMMA GEMM + band-skip transcendental epilogue ----
__global__ __launch_bounds__(256, 2) void hyper_gemm_kernel() {
    extern __shared__ __align__(16) char sm[];
    const uint32_t sbase = smem_u32(sm);
    const int tid  = threadIdx.x;
    const int wid  = tid >> 5;
    const int lane = tid & 31;
    const int r0 = blockIdx.y * TM;
    const int c0 = blockIdx.x * TN;

    #pragma unroll
    for (int it = 0; it < 8; ++it) {
        int idx = tid + it * 256;
        int row = idx >> 4, ch = idx & 15;
        uint32_t o = (uint32_t)row * LDT_B + (uint32_t)ch * 16u;
        *(uint4*)(sm + SM_A + o) = *(const uint4*)(g_A + (size_t)(r0 + row) * KDIM + ch * 8);
        *(uint4*)(sm + SM_B + o) = *(const uint4*)(g_B + (size_t)(c0 + row) * KDIM + ch * 8);
    }
    if (tid < TM) ((float*)(sm + SM_A0))[tid] = g_a0[r0 + tid];
    else if (tid < TM + TN) ((float*)(sm + SM_B0))[tid - TM] = g_b0[c0 + tid - TM];
    __syncthreads();

    const int mw = (wid & 3) * 32;
    const int nw = (wid >> 2) * 64;

    float acc[2][8][4];
    #pragma unroll
    for (int mi = 0; mi < 2; ++mi)
        #pragma unroll
        for (int ni = 0; ni < 8; ++ni)
            #pragma unroll
            for (int q = 0; q < 4; ++q) acc[mi][ni][q] = 0.f;

    const int lane8 = lane & 7, lm = lane >> 3;
    const uint32_t aAddrBase = sbase + SM_A
        + (uint32_t)(mw + ((lm & 1) << 3) + lane8) * LDT_B + (uint32_t)((lm >> 1) << 4);
    const uint32_t bAddrBase = sbase + SM_B
        + (uint32_t)(nw + ((lm >> 1) << 3) + lane8) * LDT_B + (uint32_t)((lm & 1) << 4);

    #pragma unroll
    for (int ks = 0; ks < 8; ++ks) {
        uint32_t a[2][4], b[8][2];
        ldsm_x4(a[0][0], a[0][1], a[0][2], a[0][3], aAddrBase + ks * 32u);
        ldsm_x4(a[1][0], a[1][1], a[1][2], a[1][3], aAddrBase + ks * 32u + 16u * LDT_B);
        #pragma unroll
        for (int p = 0; p < 4; ++p)
            ldsm_x4(b[2 * p][0], b[2 * p][1], b[2 * p + 1][0], b[2 * p + 1][1],
                    bAddrBase + ks * 32u + (uint32_t)p * 16u * LDT_B);
        #pragma unroll
        for (int mi = 0; mi < 2; ++mi)
            #pragma unroll
            for (int ni = 0; ni < 8; ++ni)
                mma16816(acc[mi][ni], a[mi], b[ni]);
    }

    // ---- band-skip epilogue ----
    const float* sa0 = (const float*)(sm + SM_A0);
    const float* sb0 = (const float*)(sm + SM_B0);
    const int l4 = lane >> 2, l2 = lane & 3;

    float csum[16];
    #pragma unroll
    for (int q = 0; q < 16; ++q) csum[q] = 0.f;
    float rs[4];
    #pragma unroll
    for (int q = 0; q < 4; ++q) rs[q] = 0.f;

    #pragma unroll
    for (int mi = 0; mi < 2; ++mi) {
        const float a0A = sa0[mw + mi * 16 + l4];
        const float a0B = sa0[mw + mi * 16 + l4 + 8];
        #pragma unroll
        for (int ni = 0; ni < 8; ++ni) {
            const int colL = nw + ni * 8 + 2 * l2;
            const float b0L = sb0[colL], b0R = sb0[colL + 1];
            #pragma unroll
            for (int q = 0; q < 4; ++q) {
                const float aa = (q < 2) ? a0A : a0B;
                const float bb = (q & 1) ? b0R : b0L;
                float t = fmaf(aa, bb, -acc[mi][ni][q]);      // -inner
                const bool clamp = (t <= TC_F);
                const bool band  = (!clamp) && (t < TCUT);
                float e = clamp ? E_CLAMP : 0.f;
                if (__any_sync(0xffffffffu, band)) {
                    float tc = fmaxf(t, TC_F);
                    float u = tc + f_sqrt((tc - 1.0f) * (tc + 1.0f));
                    float ef = f_ex2(PEXP * f_lg2(u));        // exp(-acosh(t)/0.07)
                    if (!clamp) e = ef;
                }
                rs[mi * 2 + (q >> 1)] += e;
                csum[ni * 2 + (q & 1)] += e;
            }
        }
    }

    #pragma unroll
    for (int q = 0; q < 4; ++q) {
        float v = rs[q];
        v += __shfl_xor_sync(0xffffffffu, v, 1);
        v += __shfl_xor_sync(0xffffffffu, v, 2);
        if (l2 == 0)
            atomicAdd(&g_rowsum[r0 + mw + (q >> 1) * 16 + (q & 1) * 8 + l4], v);
    }
    #pragma unroll
    for (int q = 0; q < 16; ++q) {
        float v = csum[q];
        v += __shfl_xor_sync(0xffffffffu, v, 4);
        v += __shfl_xor_sync(0xffffffffu, v, 8);
        v += __shfl_xor_sync(0xffffffffu, v, 16);
        if (l4 == 0)
            atomicAdd(&g_colsum[c0 + nw + (q >> 1) * 8 + 2 * l2 + (q & 1)], v);
    }
}

// ---- loss: diag + log-sums + ticket-gated finalize (write_kernel folded in) ----
__global__ void loss_kernel(float* __restrict__ out) {
    __shared__ float red[256];
    const int i = blockIdx.x * 256 + threadIdx.x;

    float dot = 0.f;
    const __nv_bfloat16* pa = g_A + (size_t)i * KDIM;
    const __nv_bfloat16* pb = g_B + (size_t)i * KDIM;
    #pragma unroll 8
    for (int k = 0; k < KDIM; ++k)
        dot = fmaf(__bfloat162float(pa[k]), __bfloat162float(pb[k]), dot);
    float t = fmaxf(fmaf(g_a0[i], g_b0[i], -dot), TC_F);
    float s_ii = -acoshf(t) * (1.0f / 0.07f);

    float part = 0.5f * (logf(g_rowsum[i]) + logf(g_colsum[i])) - s_ii;
    red[threadIdx.x] = part;
    __syncthreads();
    for (int s = 128; s > 0; s >>= 1) {
        if (threadIdx.x < s) red[threadIdx.x] += red[threadIdx.x + s];
        __syncthreads();
    }
    if (threadIdx.x == 0) {
        atomicAdd(&g_loss, red[0]);
        __threadfence();
        unsigned tk = atomicAdd(&g_ticket, 1u);
        if (tk == gridDim.x - 1) {                 // last block: all adds visible
            float total = atomicAdd(&g_loss, 0.0f); // coherent read
            out[0] = total * (1.0f / (float)BATCH);
        }
    }
}

extern "C" void kernel_launch(void* const* d_in, const int* in_sizes, int n_in,
                              void* d_out, int out_size) {
    const float* z1 = (const float*)d_in[0];
    const float* z2 = (const float*)d_in[1];
    float* out = (float*)d_out;

    static int configured = 0;
    if (!configured) {
        cudaFuncSetAttribute(hyper_gemm_kernel, cudaFuncAttributeMaxDynamicSharedMemorySize, SMEM_BYTES);
        configured = 1;
    }

    prep_kernel<<<(BATCH * KDIM + 255) / 256, 256>>>(z1, z2);
    dim3 grid(BATCH / TN, BATCH / TM);
    hyper_gemm_kernel<<<grid, 256, SMEM_BYTES>>>();
    loss_kernel<<<BATCH / 256, 256>>>(out);
}

// round 7
// speedup vs baseline: 1.0889x; 1.0889x over previous
#include <cuda_runtime.h>
#include <cuda_bf16.h>
#include <math.h>
#include <stdint.h>

#define BATCH 8192
#define D1    129
#define KDIM  128
#define TM    128
#define TN    128

#define TC_F    1.00000095367431640625f   // fp32(1 + 1e-6)
#define X_MIN   9.5367431640625e-7f       // TC_F - 1 (exact fp32)
#define X_MAX   0.5f
// Q(x) = -C + x*(C1 + x*(C2 + x*C3)), C = 1/(0.07*ln2)
#define QC0  (-20.609640474436812f)
#define QC1  (1.7174700395364010f)        //  C/12
#define QC2  (-0.38643075889569021f)      // -3C/160
#define QC3  (0.11500915443993309f)       //  5C/896

// smem: A/B tiles with rows padded to 272B (17 x 16B groups -> conflict-free ldmatrix)
#define LDT_B   272u
#define SM_A    0u
#define SM_B    34816u
#define SM_A0   69632u
#define SM_B0   70144u
#define SMEM_BYTES 70656

// ---- device scratch (allocation-free) ----
__device__ __align__(256) __nv_bfloat16 g_A[BATCH * KDIM];
__device__ __align__(256) __nv_bfloat16 g_B[BATCH * KDIM];
__device__ float g_a0[BATCH], g_b0[BATCH];
__device__ float g_rowsum[BATCH], g_colsum[BATCH];
__device__ float g_loss;
__device__ unsigned g_ticket;

__device__ __forceinline__ uint32_t smem_u32(const void* p) {
    uint32_t a;
    asm("{ .reg .u64 t; cvta.to.shared.u64 t, %1; cvt.u32.u64 %0, t; }" : "=r"(a) : "l"(p));
    return a;
}
__device__ __forceinline__ float f_sqrt(float x) { float r; asm("sqrt.approx.f32 %0, %1;" : "=f"(r) : "f"(x)); return r; }
__device__ __forceinline__ float f_ex2(float x)  { float r; asm("ex2.approx.f32 %0, %1;"  : "=f"(r) : "f"(x)); return r; }

__device__ __forceinline__ void ldsm_x4(uint32_t& r0, uint32_t& r1, uint32_t& r2, uint32_t& r3, uint32_t addr) {
    asm volatile("ldmatrix.sync.aligned.m8n8.x4.shared.b16 {%0,%1,%2,%3}, [%4];"
                 : "=r"(r0), "=r"(r1), "=r"(r2), "=r"(r3) : "r"(addr));
}
__device__ __forceinline__ void mma16816(float* c, const uint32_t* a, const uint32_t* b) {
    asm volatile("mma.sync.aligned.m16n8k16.row.col.f32.bf16.bf16.f32 "
                 "{%0,%1,%2,%3}, {%4,%5,%6,%7}, {%8,%9}, {%0,%1,%2,%3};"
                 : "+f"(c[0]), "+f"(c[1]), "+f"(c[2]), "+f"(c[3])
                 : "r"(a[0]), "r"(a[1]), "r"(a[2]), "r"(a[3]), "r"(b[0]), "r"(b[1]));
}

// ---- prep: 8 bf16 per thread, vectorized stores; zero accumulators ----
__global__ void prep_kernel(const float* __restrict__ z1, const float* __restrict__ z2) {
    int idx = blockIdx.x * 256 + threadIdx.x;       // 0 .. BATCH*16-1
    if (idx < BATCH * 16) {
        int i = idx >> 4, ch = idx & 15;
        const float* p1 = z1 + (size_t)i * D1 + 1 + ch * 8;
        const float* p2 = z2 + (size_t)i * D1 + 1 + ch * 8;
        __nv_bfloat16 a[8], b[8];
        #pragma unroll
        for (int k = 0; k < 8; ++k) { a[k] = __float2bfloat16(p1[k]); b[k] = __float2bfloat16(p2[k]); }
        *(uint4*)(g_A + (size_t)i * KDIM + ch * 8) = *(uint4*)a;
        *(uint4*)(g_B + (size_t)i * KDIM + ch * 8) = *(uint4*)b;
    }
    if (idx < BATCH) {
        g_a0[idx] = z1[(size_t)idx * D1];
        g_b0[idx] = z2[(size_t)idx * D1];
        g_rowsum[idx] = 0.f;
        g_colsum[idx] = 0.f;
    }
    if (idx == 0) { g_loss = 0.f; g_ticket = 0u; }
}

// ---- fused HMMA GEMM + branchless 2-MUFU epilogue ----
__global__ __launch_bounds__(256, 2) void hyper_gemm_kernel() {
    extern __shared__ __align__(16) char sm[];
    const uint32_t sbase = smem_u32(sm);
    const int tid  = threadIdx.x;
    const int wid  = tid >> 5;
    const int lane = tid & 31;
    const int r0 = blockIdx.y * TM;
    const int c0 = blockIdx.x * TN;

    #pragma unroll
    for (int it = 0; it < 8; ++it) {
        int idx = tid + it * 256;
        int row = idx >> 4, ch = idx & 15;
        uint32_t o = (uint32_t)row * LDT_B + (uint32_t)ch * 16u;
        *(uint4*)(sm + SM_A + o) = *(const uint4*)(g_A + (size_t)(r0 + row) * KDIM + ch * 8);
        *(uint4*)(sm + SM_B + o) = *(const uint4*)(g_B + (size_t)(c0 + row) * KDIM + ch * 8);
    }
    if (tid < TM) ((float*)(sm + SM_A0))[tid] = g_a0[r0 + tid];
    else if (tid < TM + TN) ((float*)(sm + SM_B0))[tid - TM] = g_b0[c0 + tid - TM];
    __syncthreads();

    const int mw = (wid & 3) * 32;
    const int nw = (wid >> 2) * 64;

    float acc[2][8][4];
    #pragma unroll
    for (int mi = 0; mi < 2; ++mi)
        #pragma unroll
        for (int ni = 0; ni < 8; ++ni)
            #pragma unroll
            for (int q = 0; q < 4; ++q) acc[mi][ni][q] = 0.f;

    const int lane8 = lane & 7, lm = lane >> 3;
    const uint32_t aAddrBase = sbase + SM_A
        + (uint32_t)(mw + ((lm & 1) << 3) + lane8) * LDT_B + (uint32_t)((lm >> 1) << 4);
    const uint32_t bAddrBase = sbase + SM_B
        + (uint32_t)(nw + ((lm >> 1) << 3) + lane8) * LDT_B + (uint32_t)((lm & 1) << 4);

    #pragma unroll
    for (int ks = 0; ks < 8; ++ks) {
        uint32_t a[2][4], b[8][2];
        ldsm_x4(a[0][0], a[0][1], a[0][2], a[0][3], aAddrBase + ks * 32u);
        ldsm_x4(a[1][0], a[1][1], a[1][2], a[1][3], aAddrBase + ks * 32u + 16u * LDT_B);
        #pragma unroll
        for (int p = 0; p < 4; ++p)
            ldsm_x4(b[2 * p][0], b[2 * p][1], b[2 * p + 1][0], b[2 * p + 1][1],
                    bAddrBase + ks * 32u + (uint32_t)p * 16u * LDT_B);
        #pragma unroll
        for (int mi = 0; mi < 2; ++mi)
            #pragma unroll
            for (int ni = 0; ni < 8; ++ni)
                mma16816(acc[mi][ni], a[mi], b[ni]);
    }

    // ---- branchless epilogue: e = ex2( sqrt(2x) * Q(x) ), x = clamp(t-1, X_MIN, 0.5) ----
    const float* sa0 = (const float*)(sm + SM_A0);
    const float* sb0 = (const float*)(sm + SM_B0);
    const int l4 = lane >> 2, l2 = lane & 3;

    float csum[16];
    #pragma unroll
    for (int q = 0; q < 16; ++q) csum[q] = 0.f;
    float rs[4];
    #pragma unroll
    for (int q = 0; q < 4; ++q) rs[q] = 0.f;

    #pragma unroll
    for (int mi = 0; mi < 2; ++mi) {
        const float a0A = sa0[mw + mi * 16 + l4];
        const float a0B = sa0[mw + mi * 16 + l4 + 8];
        #pragma unroll
        for (int ni = 0; ni < 8; ++ni) {
            const int colL = nw + ni * 8 + 2 * l2;
            const float b0L = sb0[colL], b0R = sb0[colL + 1];
            #pragma unroll
            for (int q = 0; q < 4; ++q) {
                const float aa = (q < 2) ? a0A : a0B;
                const float bb = (q & 1) ? b0R : b0L;
                float t = fmaf(aa, bb, -acc[mi][ni][q]);     // -inner
                float x = fminf(fmaxf(t - 1.0f, X_MIN), X_MAX);
                float w = f_sqrt(x + x);                      // sqrt(2x)
                float Qx = fmaf(x, fmaf(x, fmaf(x, QC3, QC2), QC1), QC0);
                float e = f_ex2(w * Qx);                      // exp(-acosh(t)/0.07)
                rs[mi * 2 + (q >> 1)] += e;
                csum[ni * 2 + (q & 1)] += e;
            }
        }
    }

    #pragma unroll
    for (int q = 0; q < 4; ++q) {
        float v = rs[q];
        v += __shfl_xor_sync(0xffffffffu, v, 1);
        v += __shfl_xor_sync(0xffffffffu, v, 2);
        if (l2 == 0)
            atomicAdd(&g_rowsum[r0 + mw + (q >> 1) * 16 + (q & 1) * 8 + l4], v);
    }
    #pragma unroll
    for (int q = 0; q < 16; ++q) {
        float v = csum[q];
        v += __shfl_xor_sync(0xffffffffu, v, 4);
        v += __shfl_xor_sync(0xffffffffu, v, 8);
        v += __shfl_xor_sync(0xffffffffu, v, 16);
        if (l4 == 0)
            atomicAdd(&g_colsum[c0 + nw + (q >> 1) * 8 + 2 * l2 + (q & 1)], v);
    }
}

// ---- loss: diag + log-sums + ticket-gated finalize ----
__global__ void loss_kernel(float* __restrict__ out) {
    __shared__ float red[256];
    const int i = blockIdx.x * 256 + threadIdx.x;

    float dot = 0.f;
    const __nv_bfloat16* pa = g_A + (size_t)i * KDIM;
    const __nv_bfloat16* pb = g_B + (size_t)i * KDIM;
    #pragma unroll 8
    for (int k = 0; k < KDIM; ++k)
        dot = fmaf(__bfloat162float(pa[k]), __bfloat162float(pb[k]), dot);
    float t = fmaxf(fmaf(g_a0[i], g_b0[i], -dot), TC_F);
    float s_ii = -acoshf(t) * (1.0f / 0.07f);

    float part = 0.5f * (logf(g_rowsum[i]) + logf(g_colsum[i])) - s_ii;
    red[threadIdx.x] = part;
    __syncthreads();
    for (int s = 128; s > 0; s >>= 1) {
        if (threadIdx.x < s) red[threadIdx.x] += red[threadIdx.x + s];
        __syncthreads();
    }
    if (threadIdx.x == 0) {
        atomicAdd(&g_loss, red[0]);
        __threadfence();
        unsigned tk = atomicAdd(&g_ticket, 1u);
        if (tk == gridDim.x - 1) {
            float total = atomicAdd(&g_loss, 0.0f);
            out[0] = total * (1.0f / (float)BATCH);
        }
    }
}

extern "C" void kernel_launch(void* const* d_in, const int* in_sizes, int n_in,
                              void* d_out, int out_size) {
    const float* z1 = (const float*)d_in[0];
    const float* z2 = (const float*)d_in[1];
    float* out = (float*)d_out;

    static int configured = 0;
    if (!configured) {
        cudaFuncSetAttribute(hyper_gemm_kernel, cudaFuncAttributeMaxDynamicSharedMemorySize, SMEM_BYTES);
        configured = 1;
    }

    prep_kernel<<<(BATCH * 16 + 255) / 256, 256>>>(z1, z2);
    dim3 grid(BATCH / TN, BATCH / TM);
    hyper_gemm_kernel<<<grid, 256, SMEM_BYTES>>>();
    loss_kernel<<<BATCH / 256, 256>>>(out);
}

// round 8
// speedup vs baseline: 1.1852x; 1.0885x over previous
#include <cuda_runtime.h>
#include <cuda_bf16.h>
#include <math.h>
#include <stdint.h>

#define BATCH 8192
#define D1    129
#define KDIM  128
#define TM    128
#define TN    128

#define TC_F    1.00000095367431640625f   // fp32(1 + 1e-6) = 1 + 2^-20
#define E_CLAMP 0.9804636f                // exp(-acosh(1+2^-20)/0.07)
// R(x) = sqrt(2)*(-C + C/12 x - 3C/160 x^2), C = 1/(0.07 ln2); e = ex2(sqrt(x)*R(x))
#define R0 (-29.1468383f)
#define R1 (2.42890319f)
#define R2 (-0.54650322f)

// smem: A/B tiles with rows padded to 272B (17 x 16B groups -> conflict-free ldmatrix)
#define LDT_B   272u
#define SM_A    0u
#define SM_B    34816u
#define SM_A0   69632u
#define SM_B0   70144u
#define SMEM_BYTES 70656

// ---- device scratch (allocation-free) ----
__device__ __align__(256) __nv_bfloat16 g_A[BATCH * KDIM];
__device__ __align__(256) __nv_bfloat16 g_B[BATCH * KDIM];   // stores -z2 (metric+bias fold)
__device__ float g_a0[BATCH], g_b0[BATCH];
__device__ float g_rowsum[BATCH], g_colsum[BATCH];
__device__ float g_loss;
__device__ unsigned g_ticket;

__device__ __forceinline__ uint32_t smem_u32(const void* p) {
    uint32_t a;
    asm("{ .reg .u64 t; cvta.to.shared.u64 t, %1; cvt.u32.u64 %0, t; }" : "=r"(a) : "l"(p));
    return a;
}
__device__ __forceinline__ float f_sqrt(float x) { float r; asm("sqrt.approx.f32 %0, %1;" : "=f"(r) : "f"(x)); return r; }
__device__ __forceinline__ float f_ex2(float x)  { float r; asm("ex2.approx.f32 %0, %1;"  : "=f"(r) : "f"(x)); return r; }

__device__ __forceinline__ void cp_async16(uint32_t dst, const void* src) {
    asm volatile("cp.async.ca.shared.global [%0], [%1], 16;" :: "r"(dst), "l"(src));
}
__device__ __forceinline__ void cp_async_wait_all() {
    asm volatile("cp.async.commit_group;");
    asm volatile("cp.async.wait_group 0;");
}

__device__ __forceinline__ void ldsm_x4(uint32_t& r0, uint32_t& r1, uint32_t& r2, uint32_t& r3, uint32_t addr) {
    asm volatile("ldmatrix.sync.aligned.m8n8.x4.shared.b16 {%0,%1,%2,%3}, [%4];"
                 : "=r"(r0), "=r"(r1), "=r"(r2), "=r"(r3) : "r"(addr));
}
__device__ __forceinline__ void mma16816(float* c, const uint32_t* a, const uint32_t* b) {
    asm volatile("mma.sync.aligned.m16n8k16.row.col.f32.bf16.bf16.f32 "
                 "{%0,%1,%2,%3}, {%4,%5,%6,%7}, {%8,%9}, {%0,%1,%2,%3};"
                 : "+f"(c[0]), "+f"(c[1]), "+f"(c[2]), "+f"(c[3])
                 : "r"(a[0]), "r"(a[1]), "r"(a[2]), "r"(a[3]), "r"(b[0]), "r"(b[1]));
}

// ---- prep: bf16 operands (k=1..128), B NEGATED; k=0 coords; zero accumulators ----
__global__ void prep_kernel(const float* __restrict__ z1, const float* __restrict__ z2) {
    int idx = blockIdx.x * 256 + threadIdx.x;
    if (idx < BATCH * KDIM) {
        int i = idx >> 7, kk = idx & 127;
        g_A[idx] = __float2bfloat16(z1[(size_t)i * D1 + 1 + kk]);
        g_B[idx] = __float2bfloat16(-z2[(size_t)i * D1 + 1 + kk]);
    }
    if (idx < BATCH) {
        g_a0[idx] = z1[(size_t)idx * D1];
        g_b0[idx] = z2[(size_t)idx * D1];
        g_rowsum[idx] = 0.f;
        g_colsum[idx] = 0.f;
    }
    if (idx == 0) { g_loss = 0.f; g_ticket = 0u; }
}

// ---- fused HMMA GEMM + 9-op branchless epilogue ----
__global__ __launch_bounds__(256, 2) void hyper_gemm_kernel() {
    extern __shared__ __align__(16) char sm[];
    const uint32_t sbase = smem_u32(sm);
    const int tid  = threadIdx.x;
    const int wid  = tid >> 5;
    const int lane = tid & 31;
    const int r0 = blockIdx.y * TM;
    const int c0 = blockIdx.x * TN;

    // cp.async tile staging (fire-and-forget, no LDG->STS register round trip)
    #pragma unroll
    for (int it = 0; it < 8; ++it) {
        int idx = tid + it * 256;
        int row = idx >> 4, ch = idx & 15;
        uint32_t o = (uint32_t)row * LDT_B + (uint32_t)ch * 16u;
        cp_async16(sbase + SM_A + o, g_A + (size_t)(r0 + row) * KDIM + ch * 8);
        cp_async16(sbase + SM_B + o, g_B + (size_t)(c0 + row) * KDIM + ch * 8);
    }
    if (tid < TM) ((float*)(sm + SM_A0))[tid] = g_a0[r0 + tid];
    else if (tid < TM + TN) ((float*)(sm + SM_B0))[tid - TM] = g_b0[c0 + tid - TM];
    cp_async_wait_all();
    __syncthreads();

    const int mw = (wid & 3) * 32;
    const int nw = (wid >> 2) * 64;

    // acc init -1.0: MMA (with negated B) yields acc = -dot - 1, so x = fma(a0,b0,acc) = t-1
    float acc[2][8][4];
    #pragma unroll
    for (int mi = 0; mi < 2; ++mi)
        #pragma unroll
        for (int ni = 0; ni < 8; ++ni)
            #pragma unroll
            for (int q = 0; q < 4; ++q) acc[mi][ni][q] = -1.0f;

    const int lane8 = lane & 7, lm = lane >> 3;
    const uint32_t aAddrBase = sbase + SM_A
        + (uint32_t)(mw + ((lm & 1) << 3) + lane8) * LDT_B + (uint32_t)((lm >> 1) << 4);
    const uint32_t bAddrBase = sbase + SM_B
        + (uint32_t)(nw + ((lm >> 1) << 3) + lane8) * LDT_B + (uint32_t)((lm & 1) << 4);

    #pragma unroll
    for (int ks = 0; ks < 8; ++ks) {
        uint32_t a[2][4], b[8][2];
        ldsm_x4(a[0][0], a[0][1], a[0][2], a[0][3], aAddrBase + ks * 32u);
        ldsm_x4(a[1][0], a[1][1], a[1][2], a[1][3], aAddrBase + ks * 32u + 16u * LDT_B);
        #pragma unroll
        for (int p = 0; p < 4; ++p)
            ldsm_x4(b[2 * p][0], b[2 * p][1], b[2 * p + 1][0], b[2 * p + 1][1],
                    bAddrBase + ks * 32u + (uint32_t)p * 16u * LDT_B);
        #pragma unroll
        for (int mi = 0; mi < 2; ++mi)
            #pragma unroll
            for (int ni = 0; ni < 8; ++ni)
                mma16816(acc[mi][ni], a[mi], b[ni]);
    }

    // ---- epilogue: e = fmin(ex2(sqrt(x) * R(x)), E_CLAMP) ----
    // x<0: sqrt->NaN->fmin returns E_CLAMP (exact clamp semantics). No upper clamp needed.
    const float* sa0 = (const float*)(sm + SM_A0);
    const float* sb0 = (const float*)(sm + SM_B0);
    const int l4 = lane >> 2, l2 = lane & 3;

    float csum[16];
    #pragma unroll
    for (int q = 0; q < 16; ++q) csum[q] = 0.f;
    float rs[4];
    #pragma unroll
    for (int q = 0; q < 4; ++q) rs[q] = 0.f;

    #pragma unroll
    for (int mi = 0; mi < 2; ++mi) {
        const float a0A = sa0[mw + mi * 16 + l4];
        const float a0B = sa0[mw + mi * 16 + l4 + 8];
        #pragma unroll
        for (int ni = 0; ni < 8; ++ni) {
            const int colL = nw + ni * 8 + 2 * l2;
            const float b0L = sb0[colL], b0R = sb0[colL + 1];
            #pragma unroll
            for (int q = 0; q < 4; ++q) {
                const float aa = (q < 2) ? a0A : a0B;
                const float bb = (q & 1) ? b0R : b0L;
                float x  = fmaf(aa, bb, acc[mi][ni][q]);       // t - 1
                float w  = f_sqrt(x);
                float Rx = fmaf(x, fmaf(x, R2, R1), R0);
                float e  = fminf(f_ex2(w * Rx), E_CLAMP);
                rs[mi * 2 + (q >> 1)] += e;
                csum[ni * 2 + (q & 1)] += e;
            }
        }
    }

    #pragma unroll
    for (int q = 0; q < 4; ++q) {
        float v = rs[q];
        v += __shfl_xor_sync(0xffffffffu, v, 1);
        v += __shfl_xor_sync(0xffffffffu, v, 2);
        if (l2 == 0)
            atomicAdd(&g_rowsum[r0 + mw + (q >> 1) * 16 + (q & 1) * 8 + l4], v);
    }
    #pragma unroll
    for (int q = 0; q < 16; ++q) {
        float v = csum[q];
        v += __shfl_xor_sync(0xffffffffu, v, 4);
        v += __shfl_xor_sync(0xffffffffu, v, 8);
        v += __shfl_xor_sync(0xffffffffu, v, 16);
        if (l4 == 0)
            atomicAdd(&g_colsum[c0 + nw + (q >> 1) * 8 + 2 * l2 + (q & 1)], v);
    }
}

// ---- loss: diag + log-sums + ticket-gated finalize ----
__global__ void loss_kernel(float* __restrict__ out) {
    __shared__ float red[256];
    const int i = blockIdx.x * 256 + threadIdx.x;

    float dotn = 0.f;                                  // accumulates -dot (g_B negated)
    const __nv_bfloat16* pa = g_A + (size_t)i * KDIM;
    const __nv_bfloat16* pb = g_B + (size_t)i * KDIM;
    #pragma unroll 8
    for (int k = 0; k < KDIM; ++k)
        dotn = fmaf(__bfloat162float(pa[k]), __bfloat162float(pb[k]), dotn);
    float t = fmaxf(fmaf(g_a0[i], g_b0[i], dotn), TC_F);
    float s_ii = -acoshf(t) * (1.0f / 0.07f);

    float part = 0.5f * (logf(g_rowsum[i]) + logf(g_colsum[i])) - s_ii;
    red[threadIdx.x] = part;
    __syncthreads();
    for (int s = 128; s > 0; s >>= 1) {
        if (threadIdx.x < s) red[threadIdx.x] += red[threadIdx.x + s];
        __syncthreads();
    }
    if (threadIdx.x == 0) {
        atomicAdd(&g_loss, red[0]);
        __threadfence();
        unsigned tk = atomicAdd(&g_ticket, 1u);
        if (tk == gridDim.x - 1) {
            float total = atomicAdd(&g_loss, 0.0f);
            out[0] = total * (1.0f / (float)BATCH);
        }
    }
}

extern "C" void kernel_launch(void* const* d_in, const int* in_sizes, int n_in,
                              void* d_out, int out_size) {
    const float* z1 = (const float*)d_in[0];
    const float* z2 = (const float*)d_in[1];
    float* out = (float*)d_out;

    static int configured = 0;
    if (!configured) {
        cudaFuncSetAttribute(hyper_gemm_kernel, cudaFuncAttributeMaxDynamicSharedMemorySize, SMEM_BYTES);
        configured = 1;
    }

    prep_kernel<<<(BATCH * KDIM + 255) / 256, 256>>>(z1, z2);
    dim3 grid(BATCH / TN, BATCH / TM);
    hyper_gemm_kernel<<<grid, 256, SMEM_BYTES>>>();
    loss_kernel<<<BATCH / 256, 256>>>(out);
}

// round 9
// speedup vs baseline: 1.2383x; 1.0448x over previous
#include <cuda_runtime.h>
#include <cuda_bf16.h>
#include <math.h>
#include <stdint.h>

#define BATCH 8192
#define D1    129
#define KDIM  128
#define TM    128
#define TN    128
#define NTILE 4096          // 64 x 64 tile grid

#define TC_F    1.00000095367431640625f   // fp32(1 + 1e-6)
#define E_CLAMP 0.9804636f                // exp(-acosh(1+2^-20)/0.07)
// R(x) = sqrt(2)*(-C + C/12 x - 3C/160 x^2), C = 1/(0.07 ln2); e = ex2(sqrt(x)*R(x))
#define R0 (-29.1468383f)
#define R1 (2.42890319f)
#define R2 (-0.54650322f)

// smem layout (byte offsets). Rows padded to 272B -> conflict-free ldmatrix.
#define LDT_B    272u
#define SM_A     0u          // A tile: 128*272 = 34816 (single, row-resident)
#define SM_BB0   34816u      // B tile buf0
#define SM_BB1   69632u      // B tile buf1
#define SM_A0F   104448u     // a0: 2 x 128 floats (row-change double buffer)
#define SM_B0F   105472u     // b0: 2 x 128 floats (per-tile double buffer)
#define SMEM_BYTES 106496

// ---- device scratch (allocation-free) ----
__device__ __align__(256) __nv_bfloat16 g_A[BATCH * KDIM];
__device__ __align__(256) __nv_bfloat16 g_B[BATCH * KDIM];   // stores -z2 (metric+bias fold)
__device__ float g_a0[BATCH], g_b0[BATCH];
__device__ float g_rowsum[BATCH], g_colsum[BATCH];
__device__ float g_loss;
__device__ unsigned g_ticket;

__device__ __forceinline__ uint32_t smem_u32(const void* p) {
    uint32_t a;
    asm("{ .reg .u64 t; cvta.to.shared.u64 t, %1; cvt.u32.u64 %0, t; }" : "=r"(a) : "l"(p));
    return a;
}
__device__ __forceinline__ float f_sqrt(float x) { float r; asm("sqrt.approx.f32 %0, %1;" : "=f"(r) : "f"(x)); return r; }
__device__ __forceinline__ float f_ex2(float x)  { float r; asm("ex2.approx.f32 %0, %1;"  : "=f"(r) : "f"(x)); return r; }

__device__ __forceinline__ void cp_async16(uint32_t dst, const void* src) {
    asm volatile("cp.async.ca.shared.global [%0], [%1], 16;" :: "r"(dst), "l"(src));
}
__device__ __forceinline__ void cp_commit()  { asm volatile("cp.async.commit_group;"); }
__device__ __forceinline__ void cp_wait_all(){ asm volatile("cp.async.wait_group 0;"); }

__device__ __forceinline__ void ldsm_x4(uint32_t& r0, uint32_t& r1, uint32_t& r2, uint32_t& r3, uint32_t addr) {
    asm volatile("ldmatrix.sync.aligned.m8n8.x4.shared.b16 {%0,%1,%2,%3}, [%4];"
                 : "=r"(r0), "=r"(r1), "=r"(r2), "=r"(r3) : "r"(addr));
}
__device__ __forceinline__ void mma16816(float* c, const uint32_t* a, const uint32_t* b) {
    asm volatile("mma.sync.aligned.m16n8k16.row.col.f32.bf16.bf16.f32 "
                 "{%0,%1,%2,%3}, {%4,%5,%6,%7}, {%8,%9}, {%0,%1,%2,%3};"
                 : "+f"(c[0]), "+f"(c[1]), "+f"(c[2]), "+f"(c[3])
                 : "r"(a[0]), "r"(a[1]), "r"(a[2]), "r"(a[3]), "r"(b[0]), "r"(b[1]));
}

// ---- prep: flat coalesced pass over the 129-stride inputs ----
__global__ void prep_kernel(const float* __restrict__ z1, const float* __restrict__ z2) {
    int idx = blockIdx.x * 256 + threadIdx.x;
    if (idx < BATCH * D1) {
        int i = idx / D1;
        int k = idx - i * D1;
        float v1 = z1[idx], v2 = z2[idx];
        if (k == 0) { g_a0[i] = v1; g_b0[i] = v2; }
        else {
            g_A[(size_t)i * KDIM + k - 1] = __float2bfloat16(v1);
            g_B[(size_t)i * KDIM + k - 1] = __float2bfloat16(-v2);
        }
    }
    if (idx < BATCH) { g_rowsum[idx] = 0.f; g_colsum[idx] = 0.f; }
    if (idx == 0) { g_loss = 0.f; g_ticket = 0u; }
}

// ---- helpers to issue tile prefetches ----
__device__ __forceinline__ void issue_B(uint32_t sbase, uint32_t buf_off, int c0, int tid) {
    #pragma unroll
    for (int it = 0; it < 8; ++it) {
        int idx = tid + it * 256;
        int row = idx >> 4, ch = idx & 15;
        cp_async16(sbase + buf_off + (uint32_t)row * LDT_B + (uint32_t)ch * 16u,
                   g_B + (size_t)(c0 + row) * KDIM + ch * 8);
    }
}
__device__ __forceinline__ void issue_A(uint32_t sbase, int r0, int tid) {
    #pragma unroll
    for (int it = 0; it < 8; ++it) {
        int idx = tid + it * 256;
        int row = idx >> 4, ch = idx & 15;
        cp_async16(sbase + SM_A + (uint32_t)row * LDT_B + (uint32_t)ch * 16u,
                   g_A + (size_t)(r0 + row) * KDIM + ch * 8);
    }
}
__device__ __forceinline__ void issue_b0(uint32_t sbase, int cur, int c0, int tid) {
    if (tid < 32) cp_async16(sbase + SM_B0F + (uint32_t)cur * 512u + (uint32_t)tid * 16u,
                             g_b0 + c0 + tid * 4);
}
__device__ __forceinline__ void issue_a0(uint32_t sbase, int aidx, int r0, int tid) {
    if (tid >= 32 && tid < 64)
        cp_async16(sbase + SM_A0F + (uint32_t)aidx * 512u + (uint32_t)(tid - 32) * 16u,
                   g_a0 + r0 + (tid - 32) * 4);
}

// ---- persistent fused HMMA GEMM + branchless epilogue ----
__global__ __launch_bounds__(256, 2) void hyper_gemm_kernel(int ncta) {
    extern __shared__ __align__(16) char sm[];
    const uint32_t sbase = smem_u32(sm);
    const int tid  = threadIdx.x;
    const int wid  = tid >> 5;
    const int lane = tid & 31;

    const int start = (int)(((long long)blockIdx.x * NTILE) / ncta);
    const int end   = (int)(((long long)(blockIdx.x + 1) * NTILE) / ncta);

    const int mw = (wid & 3) * 32;
    const int nw = (wid >> 2) * 64;
    const int lane8 = lane & 7, lm = lane >> 3;
    const int l4 = lane >> 2, l2 = lane & 3;

    const uint32_t aOff = (uint32_t)(mw + ((lm & 1) << 3) + lane8) * LDT_B + (uint32_t)((lm >> 1) << 4);
    const uint32_t bOff = (uint32_t)(nw + ((lm >> 1) << 3) + lane8) * LDT_B + (uint32_t)((lm & 1) << 4);

    int cur = 0, aidx = 0;
    int tr_cur = start >> 6;

    // prologue: A(row) + a0, B(first tile) + b0
    issue_A(sbase, tr_cur * TM, tid);
    issue_a0(sbase, 0, tr_cur * TM, tid);
    issue_B(sbase, SM_BB0, (start & 63) * TN, tid);
    issue_b0(sbase, 0, (start & 63) * TN, tid);
    cp_commit();

    for (int t = start; t < end; ++t) {
        const int tr = t >> 6, tc = t & 63;
        const int r0 = tr * TM, c0 = tc * TN;

        cp_wait_all();
        __syncthreads();                    // tile t data ready; all warps past t-1's MMA

        const int nt = t + 1;
        const bool have_next = (nt < end);
        const int ntr = nt >> 6, ntc = nt & 63;
        const bool rowchg = have_next && (ntr != tr);
        if (have_next && !rowchg) {         // prefetch next B under this tile's compute
            issue_B(sbase, cur ? SM_BB0 : SM_BB1, ntc * TN, tid);
            issue_b0(sbase, cur ^ 1, ntc * TN, tid);
            cp_commit();
        }

        // ---- MMA ----
        float acc[2][8][4];
        #pragma unroll
        for (int mi = 0; mi < 2; ++mi)
            #pragma unroll
            for (int ni = 0; ni < 8; ++ni)
                #pragma unroll
                for (int q = 0; q < 4; ++q) acc[mi][ni][q] = -1.0f;  // fold the "-1"

        const uint32_t aBase = sbase + SM_A + aOff;
        const uint32_t bBase = sbase + (cur ? SM_BB1 : SM_BB0) + bOff;
        #pragma unroll
        for (int ks = 0; ks < 8; ++ks) {
            uint32_t a[2][4], b[8][2];
            ldsm_x4(a[0][0], a[0][1], a[0][2], a[0][3], aBase + ks * 32u);
            ldsm_x4(a[1][0], a[1][1], a[1][2], a[1][3], aBase + ks * 32u + 16u * LDT_B);
            #pragma unroll
            for (int p = 0; p < 4; ++p)
                ldsm_x4(b[2 * p][0], b[2 * p][1], b[2 * p + 1][0], b[2 * p + 1][1],
                        bBase + ks * 32u + (uint32_t)p * 16u * LDT_B);
            #pragma unroll
            for (int mi = 0; mi < 2; ++mi)
                #pragma unroll
                for (int ni = 0; ni < 8; ++ni)
                    mma16816(acc[mi][ni], a[mi], b[ni]);
        }

        if (rowchg) {                       // all warps done reading A (uniform branch)
            __syncthreads();
            issue_A(sbase, ntr * TM, tid);
            issue_a0(sbase, aidx ^ 1, ntr * TM, tid);
            issue_B(sbase, cur ? SM_BB0 : SM_BB1, ntc * TN, tid);
            issue_b0(sbase, cur ^ 1, ntc * TN, tid);
            cp_commit();
        }

        // ---- epilogue: e = fmin(ex2(sqrt(x)*R(x)), E_CLAMP); x<0 -> NaN -> clamp ----
        const float* sa0 = (const float*)(sm + SM_A0F + aidx * 512);
        const float* sb0 = (const float*)(sm + SM_B0F + cur * 512);

        float csum[16];
        #pragma unroll
        for (int q = 0; q < 16; ++q) csum[q] = 0.f;
        float rs[4];
        #pragma unroll
        for (int q = 0; q < 4; ++q) rs[q] = 0.f;

        #pragma unroll
        for (int mi = 0; mi < 2; ++mi) {
            const float a0A = sa0[mw + mi * 16 + l4];
            const float a0B = sa0[mw + mi * 16 + l4 + 8];
            #pragma unroll
            for (int ni = 0; ni < 8; ++ni) {
                const int colL = nw + ni * 8 + 2 * l2;
                const float b0L = sb0[colL], b0R = sb0[colL + 1];
                #pragma unroll
                for (int q = 0; q < 4; ++q) {
                    const float aa = (q < 2) ? a0A : a0B;
                    const float bb = (q & 1) ? b0R : b0L;
                    float x  = fmaf(aa, bb, acc[mi][ni][q]);   // t - 1
                    float w  = f_sqrt(x);
                    float Rx = fmaf(x, fmaf(x, R2, R1), R0);
                    float e  = fminf(f_ex2(w * Rx), E_CLAMP);
                    rs[mi * 2 + (q >> 1)] += e;
                    csum[ni * 2 + (q & 1)] += e;
                }
            }
        }

        #pragma unroll
        for (int q = 0; q < 4; ++q) {
            float v = rs[q];
            v += __shfl_xor_sync(0xffffffffu, v, 1);
            v += __shfl_xor_sync(0xffffffffu, v, 2);
            if (l2 == 0)
                atomicAdd(&g_rowsum[r0 + mw + (q >> 1) * 16 + (q & 1) * 8 + l4], v);
        }
        #pragma unroll
        for (int q = 0; q < 16; ++q) {
            float v = csum[q];
            v += __shfl_xor_sync(0xffffffffu, v, 4);
            v += __shfl_xor_sync(0xffffffffu, v, 8);
            v += __shfl_xor_sync(0xffffffffu, v, 16);
            if (l4 == 0)
                atomicAdd(&g_colsum[c0 + nw + (q >> 1) * 8 + 2 * l2 + (q & 1)], v);
        }

        cur ^= 1;
        if (rowchg) aidx ^= 1;
    }
}

// ---- loss: diag + log-sums + ticket-gated finalize ----
__global__ void loss_kernel(float* __restrict__ out) {
    __shared__ float red[256];
    const int i = blockIdx.x * 256 + threadIdx.x;

    float dotn = 0.f;                                  // accumulates -dot (g_B negated)
    const __nv_bfloat16* pa = g_A + (size_t)i * KDIM;
    const __nv_bfloat16* pb = g_B + (size_t)i * KDIM;
    #pragma unroll 8
    for (int k = 0; k < KDIM; ++k)
        dotn = fmaf(__bfloat162float(pa[k]), __bfloat162float(pb[k]), dotn);
    float t = fmaxf(fmaf(g_a0[i], g_b0[i], dotn), TC_F);
    float s_ii = -acoshf(t) * (1.0f / 0.07f);

    float part = 0.5f * (logf(g_rowsum[i]) + logf(g_colsum[i])) - s_ii;
    red[threadIdx.x] = part;
    __syncthreads();
    for (int s = 128; s > 0; s >>= 1) {
        if (threadIdx.x < s) red[threadIdx.x] += red[threadIdx.x + s];
        __syncthreads();
    }
    if (threadIdx.x == 0) {
        atomicAdd(&g_loss, red[0]);
        __threadfence();
        unsigned tk = atomicAdd(&g_ticket, 1u);
        if (tk == gridDim.x - 1) {
            float total = atomicAdd(&g_loss, 0.0f);
            out[0] = total * (1.0f / (float)BATCH);
        }
    }
}

extern "C" void kernel_launch(void* const* d_in, const int* in_sizes, int n_in,
                              void* d_out, int out_size) {
    const float* z1 = (const float*)d_in[0];
    const float* z2 = (const float*)d_in[1];
    float* out = (float*)d_out;

    static int ncta = 0;
    if (ncta == 0) {
        int sms = 0;
        if (cudaDeviceGetAttribute(&sms, cudaDevAttrMultiProcessorCount, 0) != cudaSuccess || sms <= 0)
            sms = 148;
        ncta = 2 * sms;
        if (ncta > NTILE) ncta = NTILE;
        cudaFuncSetAttribute(hyper_gemm_kernel, cudaFuncAttributeMaxDynamicSharedMemorySize, SMEM_BYTES);
    }

    prep_kernel<<<(BATCH * D1 + 255) / 256, 256>>>(z1, z2);
    hyper_gemm_kernel<<<ncta, 256, SMEM_BYTES>>>(ncta);
    loss_kernel<<<BATCH / 256, 256>>>(out);
}

// round 10
// speedup vs baseline: 1.2857x; 1.0383x over previous
#include <cuda_runtime.h>
#include <cuda_bf16.h>
#include <math.h>
#include <stdint.h>

#define BATCH 8192
#define D1    129
#define KDIM  128
#define TM    128
#define TN    64
#define NTILE 8192          // 64 rows x 128 cols of 128x64 tiles

#define TC_F    1.00000095367431640625f   // fp32(1 + 1e-6)
#define E_CLAMP 0.9804636f                // exp(-acosh(1+2^-20)/0.07)
// R(x) = sqrt(2)*(-C + C/12 x - 3C/160 x^2), C = 1/(0.07 ln2); e = ex2(sqrt(x)*R(x))
#define R0 (-29.1468383f)
#define R1 (2.42890319f)
#define R2 (-0.54650322f)

// smem layout (byte offsets). Rows padded to 272B -> conflict-free ldmatrix.
#define LDT_B    272u
#define SM_A     0u          // A tile: 128*272 = 34816 (shared by both groups, row-resident)
#define SM_B     34816u      // 4 B buffers (group g, buf u at (g*2+u)*17408), 64*272 each
#define B_BUF    17408u
#define SM_A0F   104448u     // a0: 128 floats (row-scoped)
#define SM_B0F   104960u     // b0: 4 x 64 floats (per group x buf)
#define SMEM_BYTES 106240

// ---- device scratch (allocation-free) ----
__device__ __align__(256) __nv_bfloat16 g_A[BATCH * KDIM];
__device__ __align__(256) __nv_bfloat16 g_B[BATCH * KDIM];   // stores -z2 (metric+bias fold)
__device__ float g_a0[BATCH], g_b0[BATCH];
__device__ float g_rowsum[BATCH], g_colsum[BATCH];
__device__ float g_loss;
__device__ unsigned g_ticket;

__device__ __forceinline__ uint32_t smem_u32(const void* p) {
    uint32_t a;
    asm("{ .reg .u64 t; cvta.to.shared.u64 t, %1; cvt.u32.u64 %0, t; }" : "=r"(a) : "l"(p));
    return a;
}
__device__ __forceinline__ float f_sqrt(float x) { float r; asm("sqrt.approx.f32 %0, %1;" : "=f"(r) : "f"(x)); return r; }
__device__ __forceinline__ float f_ex2(float x)  { float r; asm("ex2.approx.f32 %0, %1;"  : "=f"(r) : "f"(x)); return r; }

__device__ __forceinline__ void cp_async16(uint32_t dst, const void* src) {
    asm volatile("cp.async.ca.shared.global [%0], [%1], 16;" :: "r"(dst), "l"(src));
}
__device__ __forceinline__ void cp_commit()   { asm volatile("cp.async.commit_group;"); }
__device__ __forceinline__ void cp_wait_all() { asm volatile("cp.async.wait_group 0;"); }
__device__ __forceinline__ void bar_group(int g) {
    asm volatile("bar.sync %0, %1;" :: "r"(g + 1), "r"(128) : "memory");
}

__device__ __forceinline__ void ldsm_x4(uint32_t& r0, uint32_t& r1, uint32_t& r2, uint32_t& r3, uint32_t addr) {
    asm volatile("ldmatrix.sync.aligned.m8n8.x4.shared.b16 {%0,%1,%2,%3}, [%4];"
                 : "=r"(r0), "=r"(r1), "=r"(r2), "=r"(r3) : "r"(addr));
}
__device__ __forceinline__ void mma16816(float* c, const uint32_t* a, const uint32_t* b) {
    asm volatile("mma.sync.aligned.m16n8k16.row.col.f32.bf16.bf16.f32 "
                 "{%0,%1,%2,%3}, {%4,%5,%6,%7}, {%8,%9}, {%0,%1,%2,%3};"
                 : "+f"(c[0]), "+f"(c[1]), "+f"(c[2]), "+f"(c[3])
                 : "r"(a[0]), "r"(a[1]), "r"(a[2]), "r"(a[3]), "r"(b[0]), "r"(b[1]));
}

// ---- prep: flat coalesced pass over the 129-stride inputs ----
__global__ void prep_kernel(const float* __restrict__ z1, const float* __restrict__ z2) {
    int idx = blockIdx.x * 256 + threadIdx.x;
    if (idx < BATCH * D1) {
        int i = idx / D1;
        int k = idx - i * D1;
        float v1 = z1[idx], v2 = z2[idx];
        if (k == 0) { g_a0[i] = v1; g_b0[i] = v2; }
        else {
            g_A[(size_t)i * KDIM + k - 1] = __float2bfloat16(v1);
            g_B[(size_t)i * KDIM + k - 1] = __float2bfloat16(-v2);
        }
    }
    if (idx < BATCH) { g_rowsum[idx] = 0.f; g_colsum[idx] = 0.f; }
    if (idx == 0) { g_loss = 0.f; g_ticket = 0u; }
}

// ---- persistent two-group fused HMMA GEMM + branchless epilogue ----
__global__ __launch_bounds__(256, 2) void hyper_gemm_kernel(int ncta) {
    extern __shared__ __align__(16) char sm[];
    const uint32_t sbase = smem_u32(sm);
    const int tid  = threadIdx.x;
    const int g    = tid >> 7;          // group 0/1
    const int gtid = tid & 127;
    const int wg   = gtid >> 5;         // warp in group 0..3
    const int lane = tid & 31;

    const int start = (int)(((long long)blockIdx.x * NTILE) / ncta);
    const int end   = (int)(((long long)(blockIdx.x + 1) * NTILE) / ncta);

    const int mw = wg * 32;
    const int lane8 = lane & 7, lm = lane >> 3;
    const int l4 = lane >> 2, l2 = lane & 3;

    const uint32_t aOff = (uint32_t)(mw + ((lm & 1) << 3) + lane8) * LDT_B + (uint32_t)((lm >> 1) << 4);
    const uint32_t bOff = (uint32_t)(((lm >> 1) << 3) + lane8) * LDT_B + (uint32_t)((lm & 1) << 4);

    int pos = start;
    while (pos < end) {
        const int tr = pos >> 7;
        const int r0 = tr * TM;
        const int row_end = min(end, (tr + 1) << 7);

        __syncthreads();                              // both groups done with previous row's A

        // load A strip (all 256 threads) + a0 vector
        #pragma unroll
        for (int it = 0; it < 8; ++it) {
            int idx = tid + it * 256;
            int row = idx >> 4, ch = idx & 15;
            cp_async16(sbase + SM_A + (uint32_t)row * LDT_B + (uint32_t)ch * 16u,
                       g_A + (size_t)(r0 + row) * KDIM + ch * 8);
        }
        if (tid < 32) cp_async16(sbase + SM_A0F + (uint32_t)tid * 16u, g_a0 + r0 + tid * 4);

        // first own tile of this row chunk (parity keyed to start+g)
        const int first = pos + (((start + g) ^ pos) & 1);
        const int n_own = (first < row_end) ? ((row_end - first + 1) >> 1) : 0;

        if (n_own > 0) {
            const int c0 = (first & 127) * TN;
            const uint32_t bb = sbase + SM_B + (uint32_t)(g * 2) * B_BUF;
            #pragma unroll
            for (int it = 0; it < 8; ++it) {
                int idx = gtid + it * 128;
                int row = idx >> 4, ch = idx & 15;
                cp_async16(bb + (uint32_t)row * LDT_B + (uint32_t)ch * 16u,
                           g_B + (size_t)(c0 + row) * KDIM + ch * 8);
            }
            if (gtid < 16)
                cp_async16(sbase + SM_B0F + (uint32_t)(g * 2) * 256u + (uint32_t)gtid * 16u,
                           g_b0 + c0 + gtid * 4);
        }
        cp_commit();
        cp_wait_all();
        __syncthreads();

        int cur = 0;
        for (int i = 0; i < n_own; ++i) {
            const int t = first + 2 * i;
            const int c0 = (t & 127) * TN;
            const bool more = (i + 1 < n_own);

            if (more) {                               // prefetch next own tile under this compute
                const int nc0 = ((t + 2) & 127) * TN;
                const uint32_t bb = sbase + SM_B + (uint32_t)(g * 2 + (cur ^ 1)) * B_BUF;
                #pragma unroll
                for (int it = 0; it < 8; ++it) {
                    int idx = gtid + it * 128;
                    int row = idx >> 4, ch = idx & 15;
                    cp_async16(bb + (uint32_t)row * LDT_B + (uint32_t)ch * 16u,
                               g_B + (size_t)(nc0 + row) * KDIM + ch * 8);
                }
                if (gtid < 16)
                    cp_async16(sbase + SM_B0F + (uint32_t)(g * 2 + (cur ^ 1)) * 256u + (uint32_t)gtid * 16u,
                               g_b0 + nc0 + gtid * 4);
                cp_commit();
            }

            // ---- MMA ----
            float acc[2][8][4];
            #pragma unroll
            for (int mi = 0; mi < 2; ++mi)
                #pragma unroll
                for (int ni = 0; ni < 8; ++ni)
                    #pragma unroll
                    for (int q = 0; q < 4; ++q) acc[mi][ni][q] = -1.0f;   // fold the "-1"

            const uint32_t aBase = sbase + SM_A + aOff;
            const uint32_t bBase = sbase + SM_B + (uint32_t)(g * 2 + cur) * B_BUF + bOff;
            #pragma unroll
            for (int ks = 0; ks < 8; ++ks) {
                uint32_t a[2][4], b[8][2];
                ldsm_x4(a[0][0], a[0][1], a[0][2], a[0][3], aBase + ks * 32u);
                ldsm_x4(a[1][0], a[1][1], a[1][2], a[1][3], aBase + ks * 32u + 16u * LDT_B);
                #pragma unroll
                for (int p = 0; p < 4; ++p)
                    ldsm_x4(b[2 * p][0], b[2 * p][1], b[2 * p + 1][0], b[2 * p + 1][1],
                            bBase + ks * 32u + (uint32_t)p * 16u * LDT_B);
                #pragma unroll
                for (int mi = 0; mi < 2; ++mi)
                    #pragma unroll
                    for (int ni = 0; ni < 8; ++ni)
                        mma16816(acc[mi][ni], a[mi], b[ni]);
            }

            // ---- epilogue: e = fmin(ex2(sqrt(x)*R(x)), E_CLAMP); x<0 -> NaN -> clamp ----
            const float* sa0 = (const float*)(sm + SM_A0F);
            const float* sb0 = (const float*)(sm + SM_B0F + (g * 2 + cur) * 256);

            float csum[16];
            #pragma unroll
            for (int q = 0; q < 16; ++q) csum[q] = 0.f;
            float rs[4];
            #pragma unroll
            for (int q = 0; q < 4; ++q) rs[q] = 0.f;

            #pragma unroll
            for (int mi = 0; mi < 2; ++mi) {
                const float a0A = sa0[mw + mi * 16 + l4];
                const float a0B = sa0[mw + mi * 16 + l4 + 8];
                #pragma unroll
                for (int ni = 0; ni < 8; ++ni) {
                    const int colL = ni * 8 + 2 * l2;
                    const float b0L = sb0[colL], b0R = sb0[colL + 1];
                    #pragma unroll
                    for (int q = 0; q < 4; ++q) {
                        const float aa = (q < 2) ? a0A : a0B;
                        const float bb = (q & 1) ? b0R : b0L;
                        float x  = fmaf(aa, bb, acc[mi][ni][q]);   // t - 1
                        float w  = f_sqrt(x);
                        float Rx = fmaf(x, fmaf(x, R2, R1), R0);
                        float e  = fminf(f_ex2(w * Rx), E_CLAMP);
                        rs[mi * 2 + (q >> 1)] += e;
                        csum[ni * 2 + (q & 1)] += e;
                    }
                }
            }

            #pragma unroll
            for (int q = 0; q < 4; ++q) {
                float v = rs[q];
                v += __shfl_xor_sync(0xffffffffu, v, 1);
                v += __shfl_xor_sync(0xffffffffu, v, 2);
                if (l2 == 0)
                    atomicAdd(&g_rowsum[r0 + mw + (q >> 1) * 16 + (q & 1) * 8 + l4], v);
            }
            #pragma unroll
            for (int q = 0; q < 16; ++q) {
                float v = csum[q];
                v += __shfl_xor_sync(0xffffffffu, v, 4);
                v += __shfl_xor_sync(0xffffffffu, v, 8);
                v += __shfl_xor_sync(0xffffffffu, v, 16);
                if (l4 == 0)
                    atomicAdd(&g_colsum[c0 + (q >> 1) * 8 + 2 * l2 + (q & 1)], v);
            }

            if (more) { cp_wait_all(); bar_group(g); }    // next buffer ready; group done with cur
            cur ^= 1;
        }

        pos = row_end;
    }
}

// ---- loss: diag + log-sums + ticket-gated finalize ----
__global__ void loss_kernel(float* __restrict__ out) {
    __shared__ float red[256];
    const int i = blockIdx.x * 256 + threadIdx.x;

    float dotn = 0.f;                                  // accumulates -dot (g_B negated)
    const __nv_bfloat16* pa = g_A + (size_t)i * KDIM;
    const __nv_bfloat16* pb = g_B + (size_t)i * KDIM;
    #pragma unroll 8
    for (int k = 0; k < KDIM; ++k)
        dotn = fmaf(__bfloat162float(pa[k]), __bfloat162float(pb[k]), dotn);
    float t = fmaxf(fmaf(g_a0[i], g_b0[i], dotn), TC_F);
    float s_ii = -acoshf(t) * (1.0f / 0.07f);

    float part = 0.5f * (logf(g_rowsum[i]) + logf(g_colsum[i])) - s_ii;
    red[threadIdx.x] = part;
    __syncthreads();
    for (int s = 128; s > 0; s >>= 1) {
        if (threadIdx.x < s) red[threadIdx.x] += red[threadIdx.x + s];
        __syncthreads();
    }
    if (threadIdx.x == 0) {
        atomicAdd(&g_loss, red[0]);
        __threadfence();
        unsigned tk = atomicAdd(&g_ticket, 1u);
        if (tk == gridDim.x - 1) {
            float total = atomicAdd(&g_loss, 0.0f);
            out[0] = total * (1.0f / (float)BATCH);
        }
    }
}

extern "C" void kernel_launch(void* const* d_in, const int* in_sizes, int n_in,
                              void* d_out, int out_size) {
    const float* z1 = (const float*)d_in[0];
    const float* z2 = (const float*)d_in[1];
    float* out = (float*)d_out;

    static int ncta = 0;
    if (ncta == 0) {
        int sms = 0;
        if (cudaDeviceGetAttribute(&sms, cudaDevAttrMultiProcessorCount, 0) != cudaSuccess || sms <= 0)
            sms = 148;
        ncta = 2 * sms;
        if (ncta > NTILE) ncta = NTILE;
        cudaFuncSetAttribute(hyper_gemm_kernel, cudaFuncAttributeMaxDynamicSharedMemorySize, SMEM_BYTES);
    }

    prep_kernel<<<(BATCH * D1 + 255) / 256, 256>>>(z1, z2);
    hyper_gemm_kernel<<<ncta, 256, SMEM_BYTES>>>(ncta);
    loss_kernel<<<BATCH / 256, 256>>>(out);
}